// round 4
// baseline (speedup 1.0000x reference)
#include <cuda_runtime.h>
#include <cuda_bf16.h>
#include <cstdint>
#include <math.h>

#define BB 2
#define HH 16
#define SQ 2048
#define DDIM 64
#define MQ 128
#define TKEY 128
#define NTILE (SQ / TKEY)
#define NTH 256

#define RS 68                       // padded row stride in words (fp32)
#define TILE_W (TKEY * RS)          // 8704 words per tile buffer
#define W_K0 0
#define W_K1 TILE_W
#define W_V0 (2 * TILE_W)
#define W_V1 (3 * TILE_W)
#define W_M0 (4 * TILE_W)
#define W_M1 (4 * TILE_W + 128)
#define W_LS (4 * TILE_W + 256)
#define W_IV (4 * TILE_W + 384)
#define SMEM_BYTES ((4 * TILE_W + 512) * 4)

static __device__ __forceinline__ uint32_t smem_u32(const void* p) {
    uint32_t a;
    asm("{ .reg .u64 t; cvta.to.shared.u64 t, %1; cvt.u32.u64 %0, t; }" : "=r"(a) : "l"(p));
    return a;
}
static __device__ __forceinline__ void cp16(uint32_t dst, const void* src) {
    asm volatile("cp.async.cg.shared.global [%0], [%1], 16;" :: "r"(dst), "l"(src));
}
#define CP_COMMIT()   asm volatile("cp.async.commit_group;" ::: "memory")
#define CP_WAIT_ALL() asm volatile("cp.async.wait_group 0;" ::: "memory")

static __device__ __forceinline__ void mma_bf16(float* c, const uint32_t* a, const uint32_t* b) {
    asm volatile(
        "mma.sync.aligned.m16n8k16.row.col.f32.bf16.bf16.f32 "
        "{%0,%1,%2,%3}, {%4,%5,%6,%7}, {%8,%9}, {%0,%1,%2,%3};"
        : "+f"(c[0]), "+f"(c[1]), "+f"(c[2]), "+f"(c[3])
        : "r"(a[0]), "r"(a[1]), "r"(a[2]), "r"(a[3]), "r"(b[0]), "r"(b[1]));
}

static __device__ __forceinline__ void split2(float a, float b, uint32_t& hi, uint32_t& lo) {
    __nv_bfloat162 h = __floats2bfloat162_rn(a, b);
    float ra = a - __bfloat162float(__low2bfloat16(h));
    float rb = b - __bfloat162float(__high2bfloat16(h));
    __nv_bfloat162 l = __floats2bfloat162_rn(ra, rb);
    hi = *reinterpret_cast<uint32_t*>(&h);
    lo = *reinterpret_cast<uint32_t*>(&l);
}
static __device__ __forceinline__ uint32_t pack_bf16(float a, float b) {
    __nv_bfloat162 h = __floats2bfloat162_rn(a, b);
    return *reinterpret_cast<uint32_t*>(&h);
}

__global__ __launch_bounds__(NTH, 1)
void attn_mma2(const float* __restrict__ Q, const float* __restrict__ K,
               const float* __restrict__ V, const int* __restrict__ M,
               float* __restrict__ Out, float* __restrict__ W) {
    extern __shared__ __align__(16) float smf[];
    const uint32_t sb = smem_u32(smf);

    const int t    = threadIdx.x;
    const int lane = t & 31;
    const int g    = lane >> 2;
    const int t4   = lane & 3;
    const int dlo  = 2 * t4;
    const int x8   = (g & 1) << 3;     // XOR swizzle amount for this lane's key rows (QK)
    const int qb   = (t >> 5) * 16;

    const int qt = blockIdx.x;
    const int bh = blockIdx.y;
    const int b  = bh / HH;

    const float* qg = Q + ((size_t)bh * SQ + (size_t)qt * MQ) * DDIM;
    const float* kg = K + (size_t)bh * SQ * DDIM;
    const float* vg = V + (size_t)bh * SQ * DDIM;
    const int*   mg = M + b * SQ;

    // ---- tile prefetchers (cp.async, raw fp32, 32B XOR swizzle on odd rows) ----
    auto pf_tile = [&](uint32_t dstw, const float* gbase) {
        #pragma unroll
        for (int i = 0; i < 8; i++) {
            int idx = i * NTH + t;            // 0..2047
            int row = idx >> 4, c = idx & 15;
            uint32_t w = dstw + (uint32_t)row * RS + (uint32_t)((c * 4) ^ ((row & 1) << 3));
            cp16(sb + w * 4, gbase + row * DDIM + c * 4);
        }
    };
    auto pf_mask = [&](uint32_t dstw, const int* gm) {
        if (t < 32) cp16(sb + (dstw + (uint32_t)t * 4) * 4, gm + t * 4);
    };

    // kick off tile 0 (K + mask) immediately
    pf_tile(W_K0, kg);
    pf_mask(W_M0, mg);
    CP_COMMIT();

    // ---- persistent Q A-fragments (hi/lo) ----
    uint32_t AH[4][4], AL[4][4];
    #pragma unroll
    for (int kc = 0; kc < 4; kc++) {
        const float* r0 = qg + (size_t)(qb + g) * DDIM + kc * 16 + dlo;
        const float* r1 = r0 + 8 * DDIM;
        float2 p0 = *(const float2*)(r0);
        float2 p1 = *(const float2*)(r1);
        float2 p2 = *(const float2*)(r0 + 8);
        float2 p3 = *(const float2*)(r1 + 8);
        split2(p0.x, p0.y, AH[kc][0], AL[kc][0]);
        split2(p1.x, p1.y, AH[kc][1], AL[kc][1]);
        split2(p2.x, p2.y, AH[kc][2], AL[kc][2]);
        split2(p3.x, p3.y, AH[kc][3], AL[kc][3]);
    }

    // ---- QK chunk kernels ----
    // 1-term (pass 1): c[nt][0..3]
    auto qk1 = [&](uint32_t kb, int kc2, float (&c)[2][4]) {
        #pragma unroll
        for (int nt = 0; nt < 2; nt++)
            c[nt][0] = c[nt][1] = c[nt][2] = c[nt][3] = 0.f;
        #pragma unroll
        for (int kcd = 0; kcd < 4; kcd++) {
            #pragma unroll
            for (int nt = 0; nt < 2; nt++) {
                const float* rp = smf + kb + (uint32_t)((kc2 * 2 + nt) * 8 + g) * RS;
                float2 k0 = *(const float2*)(rp + ((kcd * 16 + dlo) ^ x8));
                float2 k1 = *(const float2*)(rp + ((kcd * 16 + dlo + 8) ^ x8));
                uint32_t bhv[2];
                bhv[0] = pack_bf16(k0.x, k0.y);
                bhv[1] = pack_bf16(k1.x, k1.y);
                mma_bf16(c[nt], AH[kcd], bhv);
            }
        }
    };
    // 3-term split (pass 2): two independent accumulators per nt
    auto qk3 = [&](uint32_t kb, int kc2, float (&c)[2][2][4]) {
        #pragma unroll
        for (int nt = 0; nt < 2; nt++)
            #pragma unroll
            for (int s = 0; s < 2; s++)
                c[nt][s][0] = c[nt][s][1] = c[nt][s][2] = c[nt][s][3] = 0.f;
        #pragma unroll
        for (int kcd = 0; kcd < 4; kcd++) {
            #pragma unroll
            for (int nt = 0; nt < 2; nt++) {
                const float* rp = smf + kb + (uint32_t)((kc2 * 2 + nt) * 8 + g) * RS;
                float2 k0 = *(const float2*)(rp + ((kcd * 16 + dlo) ^ x8));
                float2 k1 = *(const float2*)(rp + ((kcd * 16 + dlo + 8) ^ x8));
                uint32_t bhv[2], blv[2];
                split2(k0.x, k0.y, bhv[0], blv[0]);
                split2(k1.x, k1.y, bhv[1], blv[1]);
                mma_bf16(c[nt][0], AH[kcd], bhv);
                mma_bf16(c[nt][1], AH[kcd], blv);
                mma_bf16(c[nt][1], AL[kcd], bhv);
            }
        }
    };

    // ================= PASS 1: row sums (1-term bf16 QK) =================
    float rs0 = 0.f, rs1 = 0.f;
    for (int kt = 0; kt < NTILE; kt++) {
        const uint32_t kb = (kt & 1) ? W_K1 : W_K0;
        const int* mk = (const int*)(smf + ((kt & 1) ? W_M1 : W_M0));
        CP_WAIT_ALL();
        __syncthreads();
        if (kt < NTILE - 1) {
            const uint32_t nkb = (kt & 1) ? W_K0 : W_K1;
            pf_tile(nkb, kg + (size_t)(kt + 1) * TKEY * DDIM);
            pf_mask((kt & 1) ? W_M0 : W_M1, mg + (kt + 1) * TKEY);
            CP_COMMIT();
        }
        float c1[2][2][4];
        qk1(kb, 0, c1[0]);
        #pragma unroll
        for (int kc2 = 0; kc2 < 8; kc2++) {
            if (kc2 < 7) qk1(kb, kc2 + 1, c1[(kc2 + 1) & 1]);
            float (&cc)[2][4] = c1[kc2 & 1];
            int key0 = kc2 * 16 + dlo;
            int m00 = mk[key0], m01 = mk[key0 + 1], m10 = mk[key0 + 8], m11 = mk[key0 + 9];
            rs0 += (m00 ? __expf(cc[0][0] * 0.125f) : 0.f)
                 + (m01 ? __expf(cc[0][1] * 0.125f) : 0.f)
                 + (m10 ? __expf(cc[1][0] * 0.125f) : 0.f)
                 + (m11 ? __expf(cc[1][1] * 0.125f) : 0.f);
            rs1 += (m00 ? __expf(cc[0][2] * 0.125f) : 0.f)
                 + (m01 ? __expf(cc[0][3] * 0.125f) : 0.f)
                 + (m10 ? __expf(cc[1][2] * 0.125f) : 0.f)
                 + (m11 ? __expf(cc[1][3] * 0.125f) : 0.f);
        }
    }
    rs0 += __shfl_xor_sync(0xffffffffu, rs0, 1);
    rs0 += __shfl_xor_sync(0xffffffffu, rs0, 2);
    rs1 += __shfl_xor_sync(0xffffffffu, rs1, 1);
    rs1 += __shfl_xor_sync(0xffffffffu, rs1, 2);
    if (t4 == 0) {
        smf[W_LS + qb + g] = rs0;
        smf[W_LS + qb + g + 8] = rs1;
    }
    // prefetch tile 0 (K + V + mask) for pass 2
    pf_tile(W_K0, kg);
    pf_tile(W_V0, vg);
    pf_mask(W_M0, mg);
    CP_COMMIT();
    __syncthreads();
    if (t < MQ) smf[W_IV + t] = 1.f / smf[W_LS + t];
    CP_WAIT_ALL();
    __syncthreads();

    const float inv0 = smf[W_IV + qb + g];
    const float inv1 = smf[W_IV + qb + g + 8];

    float* wr0 = W + ((size_t)bh * SQ + qt * MQ + qb + g) * SQ;
    float* wr1 = wr0 + (size_t)8 * SQ;

    float accO[8][4];
    #pragma unroll
    for (int j = 0; j < 8; j++)
        accO[j][0] = accO[j][1] = accO[j][2] = accO[j][3] = 0.f;

    // ================= PASS 2: W write + PV (pipelined) =================
    for (int kt = 0; kt < NTILE; kt++) {
        const uint32_t kb = (kt & 1) ? W_K1 : W_K0;
        const uint32_t vb = (kt & 1) ? W_V1 : W_V0;
        const int* mk = (const int*)(smf + ((kt & 1) ? W_M1 : W_M0));
        if (kt > 0) { CP_WAIT_ALL(); }
        __syncthreads();
        if (kt < NTILE - 1) {
            const uint32_t nkb = (kt & 1) ? W_K0 : W_K1;
            const uint32_t nvb = (kt & 1) ? W_V0 : W_V1;
            pf_tile(nkb, kg + (size_t)(kt + 1) * TKEY * DDIM);
            pf_tile(nvb, vg + (size_t)(kt + 1) * TKEY * DDIM);
            pf_mask((kt & 1) ? W_M0 : W_M1, mg + (kt + 1) * TKEY);
            CP_COMMIT();
        }
        const size_t ktb = (size_t)kt * TKEY;

        float cbuf[2][2][2][4];
        qk3(kb, 0, cbuf[0]);
        #pragma unroll
        for (int kc2 = 0; kc2 < 8; kc2++) {
            if (kc2 < 7) qk3(kb, kc2 + 1, cbuf[(kc2 + 1) & 1]);   // next chunk's QK in flight
            float (&cP)[2][2][4] = cbuf[kc2 & 1];

            float cf[2][4];
            #pragma unroll
            for (int nt = 0; nt < 2; nt++)
                #pragma unroll
                for (int j = 0; j < 4; j++)
                    cf[nt][j] = cP[nt][0][j] + cP[nt][1][j];

            int key0 = kc2 * 16 + dlo;
            int m00 = mk[key0], m01 = mk[key0 + 1], m10 = mk[key0 + 8], m11 = mk[key0 + 9];
            float e00 = m00 ? __expf(cf[0][0] * 0.125f) * inv0 : 0.f;
            float e01 = m01 ? __expf(cf[0][1] * 0.125f) * inv0 : 0.f;
            float e02 = m00 ? __expf(cf[0][2] * 0.125f) * inv1 : 0.f;
            float e03 = m01 ? __expf(cf[0][3] * 0.125f) * inv1 : 0.f;
            float e10 = m10 ? __expf(cf[1][0] * 0.125f) * inv0 : 0.f;
            float e11 = m11 ? __expf(cf[1][1] * 0.125f) * inv0 : 0.f;
            float e12 = m10 ? __expf(cf[1][2] * 0.125f) * inv1 : 0.f;
            float e13 = m11 ? __expf(cf[1][3] * 0.125f) * inv1 : 0.f;

            size_t cb = ktb + key0;
            *(float2*)(wr0 + cb)     = make_float2(e00, e01);
            *(float2*)(wr1 + cb)     = make_float2(e02, e03);
            *(float2*)(wr0 + cb + 8) = make_float2(e10, e11);
            *(float2*)(wr1 + cb + 8) = make_float2(e12, e13);

            uint32_t aWH[4], aWL[4];
            split2(e00, e01, aWH[0], aWL[0]);
            split2(e02, e03, aWH[1], aWL[1]);
            split2(e10, e11, aWH[2], aWL[2]);
            split2(e12, e13, aWH[3], aWL[3]);

            // PV: V B-frags from raw fp32 smem (conflict-free LDS.32 pattern)
            const float* vr0 = smf + vb + (uint32_t)(kc2 * 16 + dlo) * RS;
            uint32_t bhh[8][2], bll[8][2];
            #pragma unroll
            for (int ntd = 0; ntd < 8; ntd++) {
                int d  = ntd * 8 + g;
                int dx = d ^ 8;               // odd key rows carry the 32B XOR
                float v00 = vr0[d];
                float v01 = vr0[RS + dx];
                float v10 = vr0[8 * RS + d];
                float v11 = vr0[9 * RS + dx];
                split2(v00, v01, bhh[ntd][0], bll[ntd][0]);
                split2(v10, v11, bhh[ntd][1], bll[ntd][1]);
            }
            #pragma unroll
            for (int ntd = 0; ntd < 8; ntd++) mma_bf16(accO[ntd], aWH, bhh[ntd]);
            #pragma unroll
            for (int ntd = 0; ntd < 8; ntd++) mma_bf16(accO[ntd], aWL, bhh[ntd]);
            #pragma unroll
            for (int ntd = 0; ntd < 8; ntd++) mma_bf16(accO[ntd], aWH, bll[ntd]);
        }
    }

    // ---- output ----
    float* or0 = Out + ((size_t)bh * SQ + qt * MQ + qb + g) * DDIM + dlo;
    float* or1 = or0 + (size_t)8 * DDIM;
    #pragma unroll
    for (int ntd = 0; ntd < 8; ntd++) {
        *(float2*)(or0 + ntd * 8) = make_float2(accO[ntd][0], accO[ntd][1]);
        *(float2*)(or1 + ntd * 8) = make_float2(accO[ntd][2], accO[ntd][3]);
    }
}

extern "C" void kernel_launch(void* const* d_in, const int* in_sizes, int n_in,
                              void* d_out, int out_size) {
    const float* q = (const float*)d_in[0];
    const float* k = (const float*)d_in[1];
    const float* v = (const float*)d_in[2];
    const int*   m = (const int*)d_in[3];

    float* out = (float*)d_out;
    float* wts = out + (size_t)BB * HH * SQ * DDIM;

    cudaFuncSetAttribute(attn_mma2, cudaFuncAttributeMaxDynamicSharedMemorySize, SMEM_BYTES);
    dim3 grid(SQ / MQ, BB * HH);
    attn_mma2<<<grid, NTH, SMEM_BYTES>>>(q, k, v, m, out, wts);
}